// round 5
// baseline (speedup 1.0000x reference)
#include <cuda_runtime.h>
#include <cuda_bf16.h>
#include <cstdint>
#include <math.h>

#define S 4096
#define D 1024
#define H 16
#define HD 64
typedef __nv_bfloat16 bf16;

// ---------------- device scratch -------------------------------------------
__device__ bf16 g_Xhi[(size_t)S * D], g_Xlo[(size_t)S * D];
__device__ bf16 g_Whi[4 * (size_t)D * D], g_Wlo[4 * (size_t)D * D];
__device__ bf16 g_Qhi[(size_t)S * D], g_Qlo[(size_t)S * D];
__device__ bf16 g_Khi[(size_t)S * D], g_Klo[(size_t)S * D];
__device__ bf16 g_Vhi[(size_t)S * D], g_Vlo[(size_t)S * D];
__device__ bf16 g_Ohi[(size_t)S * D], g_Olo[(size_t)S * D];
__device__ float g_cos[S * 32], g_sin[S * 32];

// ---------------- helpers ---------------------------------------------------
__device__ __forceinline__ uint32_t smem_u32(const void* p) {
    uint32_t a;
    asm("{ .reg .u64 t; cvta.to.shared.u64 t, %1; cvt.u32.u64 %0, t; }"
        : "=r"(a) : "l"(p));
    return a;
}

__device__ __forceinline__ void cp16(uint32_t saddr, const void* g) {
    asm volatile("cp.async.cg.shared.global [%0], [%1], 16;" :: "r"(saddr), "l"(g));
}

__device__ __forceinline__ void ldsm4(uint32_t a, uint32_t r[4]) {
    asm volatile("ldmatrix.sync.aligned.m8n8.x4.shared.b16 {%0,%1,%2,%3}, [%4];"
                 : "=r"(r[0]), "=r"(r[1]), "=r"(r[2]), "=r"(r[3]) : "r"(a));
}

__device__ __forceinline__ void ldsm4t(uint32_t a, uint32_t r[4]) {
    asm volatile("ldmatrix.sync.aligned.m8n8.x4.trans.shared.b16 {%0,%1,%2,%3}, [%4];"
                 : "=r"(r[0]), "=r"(r[1]), "=r"(r[2]), "=r"(r[3]) : "r"(a));
}

__device__ __forceinline__ void mma16816(float c[4], const uint32_t a[4],
                                         uint32_t b0, uint32_t b1) {
    asm volatile(
        "mma.sync.aligned.m16n8k16.row.col.f32.bf16.bf16.f32 "
        "{%0,%1,%2,%3}, {%4,%5,%6,%7}, {%8,%9}, {%0,%1,%2,%3};"
        : "+f"(c[0]), "+f"(c[1]), "+f"(c[2]), "+f"(c[3])
        : "r"(a[0]), "r"(a[1]), "r"(a[2]), "r"(a[3]), "r"(b0), "r"(b1));
}

__device__ __forceinline__ uint32_t pack_bf2(float a, float b) {
    bf16 ha = __float2bfloat16(a), hb = __float2bfloat16(b);
    return ((uint32_t)__bfloat16_as_ushort(hb) << 16) | __bfloat16_as_ushort(ha);
}

// ---------------- split / rope-table kernels --------------------------------
__device__ __forceinline__ void split_one(const float* src, bf16* hi, bf16* lo, size_t i) {
    float x = src[i];
    bf16 h = __float2bfloat16(x);
    hi[i] = h;
    lo[i] = __float2bfloat16(x - __bfloat162float(h));
}

__global__ void split_x_kernel(const float* __restrict__ x) {
    size_t i = (size_t)blockIdx.x * 256 + threadIdx.x;
    split_one(x, g_Xhi, g_Xlo, i);
}

__global__ void split_w_kernel(const float* __restrict__ Wq, const float* __restrict__ Wk,
                               const float* __restrict__ Wv, const float* __restrict__ Wo) {
    int z = blockIdx.z;
    const float* W = (z == 0) ? Wq : (z == 1) ? Wk : (z == 2) ? Wv : Wo;
    size_t i = (size_t)blockIdx.x * 256 + threadIdx.x;
    split_one(W, g_Whi + (size_t)z * D * D, g_Wlo + (size_t)z * D * D, i);
}

__global__ void rope_table_kernel(const int* __restrict__ pos) {
    int m = blockIdx.x;
    int i = threadIdx.x;  // pair index 0..31
    double f = pow(10000.0, -(double)(2 * i) / 64.0);
    float ang = (float)pos[m] * (float)f;
    float sv, cv;
    sincosf(ang, &sv, &cv);
    g_cos[m * 32 + i] = cv;
    g_sin[m * 32 + i] = sv;
}

// ---------------- split-bf16 HMMA GEMM:  Y = A @ B^T -------------------------
// CTA 128x128, 8 warps (2x4), k-chunk 32, double-buffered cp.async.
#define MM_SP    80                 // padded row bytes (32 bf16 + 16B pad)
#define MM_MAT   (128 * MM_SP)      // 10240 B
#define MM_STAGE (4 * MM_MAT)       // Ah, Al, Bh, Bl
#define MM_SMEM  (2 * MM_STAGE)     // 81920 B

__device__ __forceinline__ void mm_load_stage(uint32_t sb, int st, int c,
                                              const bf16* A_h, const bf16* A_l,
                                              const bf16* B_h, const bf16* B_l) {
    const bf16* srcs[4] = {A_h, A_l, B_h, B_l};
    int t = threadIdx.x;
#pragma unroll
    for (int i = 0; i < 8; i++) {
        int cid = t + i * 256;                 // 0..2047
        int mi = cid >> 9;                     // matrix 0..3
        int r  = (cid >> 2) & 127;             // row 0..127
        int q  = cid & 3;                      // 16B chunk 0..3
        const bf16* g = srcs[mi] + (size_t)r * D + c * 32 + q * 8;
        cp16(sb + st * MM_STAGE + mi * MM_MAT + r * MM_SP + q * 16, g);
    }
}

__device__ __forceinline__ void mm_stage_compute(uint32_t sb, int st, int wm, int wn,
                                                 int lane, float acc[4][4][4]) {
    uint32_t so = sb + st * MM_STAGE;
    const int lr = lane & 15, lc = lane >> 4;
#pragma unroll
    for (int ks = 0; ks < 2; ks++) {
        uint32_t af[4][4], bh[4][2], bl[4][2], t4[4];
#pragma unroll
        for (int i = 0; i < 4; i++)
            ldsm4(so + 0 * MM_MAT + (wm * 64 + i * 16 + lr) * MM_SP + ks * 32 + lc * 16, af[i]);
#pragma unroll
        for (int jj = 0; jj < 2; jj++) {
            ldsm4(so + 2 * MM_MAT + (wn * 32 + jj * 16 + lr) * MM_SP + ks * 32 + lc * 16, t4);
            bh[2 * jj][0] = t4[0]; bh[2 * jj][1] = t4[2];
            bh[2 * jj + 1][0] = t4[1]; bh[2 * jj + 1][1] = t4[3];
            ldsm4(so + 3 * MM_MAT + (wn * 32 + jj * 16 + lr) * MM_SP + ks * 32 + lc * 16, t4);
            bl[2 * jj][0] = t4[0]; bl[2 * jj][1] = t4[2];
            bl[2 * jj + 1][0] = t4[1]; bl[2 * jj + 1][1] = t4[3];
        }
#pragma unroll
        for (int i = 0; i < 4; i++)
#pragma unroll
            for (int j = 0; j < 4; j++) {
                mma16816(acc[i][j], af[i], bh[j][0], bh[j][1]);   // Ah*Bh
                mma16816(acc[i][j], af[i], bl[j][0], bl[j][1]);   // Ah*Bl
            }
#pragma unroll
        for (int i = 0; i < 4; i++)
            ldsm4(so + 1 * MM_MAT + (wm * 64 + i * 16 + lr) * MM_SP + ks * 32 + lc * 16, af[i]);
#pragma unroll
        for (int i = 0; i < 4; i++)
#pragma unroll
            for (int j = 0; j < 4; j++)
                mma16816(acc[i][j], af[i], bh[j][0], bh[j][1]);   // Al*Bh
    }
}

// mode 0: rope + bf16 hi/lo out; mode 1: bf16 hi/lo out; mode 2: fp32 out.
__device__ void mm_body(const bf16* Ah, const bf16* Al, const bf16* Bh, const bf16* Bl,
                        int mode, float* outF, bf16* outH, bf16* outL) {
    extern __shared__ char smem[];
    uint32_t sb = smem_u32(smem);
    const int tid = threadIdx.x, lane = tid & 31, wid = tid >> 5;
    const int wm = wid >> 2, wn = wid & 3;
    const int m0 = blockIdx.y * 128, n0 = blockIdx.x * 128;

    const bf16* A_h = Ah + (size_t)m0 * D;
    const bf16* A_l = Al + (size_t)m0 * D;
    const bf16* B_h = Bh + (size_t)n0 * D;
    const bf16* B_l = Bl + (size_t)n0 * D;

    float acc[4][4][4];
#pragma unroll
    for (int i = 0; i < 4; i++)
#pragma unroll
        for (int j = 0; j < 4; j++)
#pragma unroll
            for (int e = 0; e < 4; e++) acc[i][j][e] = 0.0f;

    mm_load_stage(sb, 0, 0, A_h, A_l, B_h, B_l);
    asm volatile("cp.async.commit_group;" ::: "memory");

#pragma unroll 1
    for (int c = 0; c < 32; c++) {
        int st = c & 1;
        if (c + 1 < 32) {
            mm_load_stage(sb, st ^ 1, c + 1, A_h, A_l, B_h, B_l);
            asm volatile("cp.async.commit_group;" ::: "memory");
            asm volatile("cp.async.wait_group 1;" ::: "memory");
        } else {
            asm volatile("cp.async.wait_group 0;" ::: "memory");
        }
        __syncthreads();
        mm_stage_compute(sb, st, wm, wn, lane, acc);
        __syncthreads();
    }

    const int g = lane >> 2, tig = lane & 3;
#pragma unroll
    for (int i = 0; i < 4; i++)
#pragma unroll
        for (int j = 0; j < 4; j++) {
            const int m = m0 + wm * 64 + i * 16 + g;
            const int n = n0 + wn * 32 + j * 8 + tig * 2;
#pragma unroll
            for (int rr = 0; rr < 2; rr++) {
                const int mm = m + rr * 8;
                float e = acc[i][j][rr * 2], o = acc[i][j][rr * 2 + 1];
                if (mode == 0) {
                    const int pidx = (n & 63) >> 1;
                    const float cv = g_cos[mm * 32 + pidx];
                    const float sv = g_sin[mm * 32 + pidx];
                    const float e2 = e * cv - o * sv;
                    const float o2 = e * sv + o * cv;
                    e = e2; o = o2;
                }
                if (mode == 2) {
                    *(float2*)(outF + (size_t)mm * D + n) = make_float2(e, o);
                } else {
                    bf16 he = __float2bfloat16(e), ho = __float2bfloat16(o);
                    float le = e - __bfloat162float(he);
                    float lo_ = o - __bfloat162float(ho);
                    *(uint32_t*)(outH + (size_t)mm * D + n) =
                        ((uint32_t)__bfloat16_as_ushort(ho) << 16) | __bfloat16_as_ushort(he);
                    *(uint32_t*)(outL + (size_t)mm * D + n) = pack_bf2(le, lo_);
                }
            }
        }
}

__global__ __launch_bounds__(256, 2) void mm_qkv_kernel() {
    const int z = blockIdx.z;
    const bf16* Bh = g_Whi + (size_t)z * D * D;
    const bf16* Bl = g_Wlo + (size_t)z * D * D;
    bf16* oh = (z == 0) ? g_Qhi : (z == 1) ? g_Khi : g_Vhi;
    bf16* ol = (z == 0) ? g_Qlo : (z == 1) ? g_Klo : g_Vlo;
    mm_body(g_Xhi, g_Xlo, Bh, Bl, (z < 2) ? 0 : 1, (float*)0, oh, ol);
}

__global__ __launch_bounds__(256, 2) void mm_out_kernel(float* __restrict__ out) {
    mm_body(g_Ohi, g_Olo, g_Whi + 3ull * D * D, g_Wlo + 3ull * D * D, 2, out, (bf16*)0, (bf16*)0);
}

// ---------------- HMMA flash attention --------------------------------------
// CTA = 128 q rows x 1 head, 8 warps (each m16). kv tiles of 64, double-buffered.
#define AT_SP    144                 // padded row bytes (64 bf16 = 128B + 16B pad)
#define AT_MAT   (64 * AT_SP)        // 9216 B
#define AT_QMAT  (128 * AT_SP)       // 18432 B (one 128-row Q matrix)
#define AT_QOFF  0
#define AT_KVOFF (2 * AT_QMAT)       // 36864
#define AT_STAGE (4 * AT_MAT)        // Kh Kl Vh Vl = 36864 B
#define AT_SMEM  (AT_KVOFF + 2 * AT_STAGE)   // 110592 B

// Q: 2 matrices (hi, lo) of 128 rows x 128B. 2048 chunks over 256 threads.
__device__ __forceinline__ void at_load_q(uint32_t sb, const bf16* gh, const bf16* gl) {
    int t = threadIdx.x;
#pragma unroll
    for (int i = 0; i < 8; i++) {
        int cid = t + i * 256;          // 0..2047
        int m = cid >> 10;              // mat 0..1
        int r = (cid >> 3) & 127;       // row
        int q = cid & 7;                // 16B chunk
        const bf16* g = (m ? gl : gh) + (size_t)r * D + q * 8;
        cp16(sb + AT_QOFF + m * AT_QMAT + r * AT_SP + q * 16, g);
    }
}

// KV stage: 4 matrices of 64 rows x 128B. 2048 chunks over 256 threads.
__device__ __forceinline__ void at_load_kv(uint32_t sdst, size_t koff) {
    const bf16* srcs[4] = {g_Khi + koff, g_Klo + koff, g_Vhi + koff, g_Vlo + koff};
    int t = threadIdx.x;
#pragma unroll
    for (int i = 0; i < 8; i++) {
        int cid = t + i * 256;          // 0..2047
        int m = cid >> 9;               // mat 0..3
        int r = (cid >> 3) & 63;        // row
        int q = cid & 7;                // 16B chunk
        cp16(sdst + m * AT_MAT + r * AT_SP + q * 16, srcs[m] + (size_t)r * D + q * 8);
    }
}

__global__ __launch_bounds__(256, 2) void attn_kernel() {
    extern __shared__ char smem[];
    uint32_t sb = smem_u32(smem);
    const int tid = threadIdx.x, lane = tid & 31, w = tid >> 5;   // w: 0..7
    const int qt = (int)gridDim.x - 1 - (int)blockIdx.x;          // heavy first
    const int h = blockIdx.y;
    const int qbase = qt * 128;
    const int lr = lane & 15, lc = lane >> 4;
    const int g = lane >> 2, tig = lane & 3;

    // G0: Q tile;  G1: KV tile 0 into stage 0
    at_load_q(sb, g_Qhi + (size_t)qbase * D + h * HD, g_Qlo + (size_t)qbase * D + h * HD);
    asm volatile("cp.async.commit_group;" ::: "memory");
    at_load_kv(sb + AT_KVOFF, (size_t)0 * D + (size_t)h * HD + (size_t)(qt * 0));
    // NOTE: kv tile 0 offset is just h*HD (kt=0)
    asm volatile("cp.async.commit_group;" ::: "memory");

    uint32_t qh[4][4], ql[4][4];
    bool qloaded = false;

    float o[8][4];
#pragma unroll
    for (int j = 0; j < 8; j++)
#pragma unroll
        for (int e = 0; e < 4; e++) o[j][e] = 0.0f;
    float m0r = -1e30f, m1r = -1e30f, l0 = 0.0f, l1 = 0.0f;

    const int nt = 2 * qt + 2;

#pragma unroll 1
    for (int kt = 0; kt < nt; kt++) {
        if (kt + 1 < nt) {
            at_load_kv(sb + AT_KVOFF + ((kt + 1) & 1) * AT_STAGE,
                       (size_t)((kt + 1) * 64) * D + (size_t)h * HD);
            asm volatile("cp.async.commit_group;" ::: "memory");
            asm volatile("cp.async.wait_group 1;" ::: "memory");
        } else {
            asm volatile("cp.async.wait_group 0;" ::: "memory");
        }
        __syncthreads();

        if (!qloaded) {
            qloaded = true;
#pragma unroll
            for (int ks = 0; ks < 4; ks++) {
                ldsm4(sb + AT_QOFF + 0 * AT_QMAT + (w * 16 + lr) * AT_SP + ks * 32 + lc * 16, qh[ks]);
                ldsm4(sb + AT_QOFF + 1 * AT_QMAT + (w * 16 + lr) * AT_SP + ks * 32 + lc * 16, ql[ks]);
            }
        }

        const uint32_t kb = sb + AT_KVOFF + (kt & 1) * AT_STAGE;
        const uint32_t sKh = kb, sKl = kb + AT_MAT, sVh = kb + 2 * AT_MAT, sVl = kb + 3 * AT_MAT;

        float s[8][4];
#pragma unroll
        for (int j = 0; j < 8; j++)
#pragma unroll
            for (int e = 0; e < 4; e++) s[j][e] = 0.0f;

        // --- S = (Qh+Ql)(Kh+Kl)^T, 3 combos ---
#pragma unroll
        for (int ks = 0; ks < 4; ks++) {
#pragma unroll
            for (int jj = 0; jj < 4; jj++) {
                uint32_t t4[4], u4[4];
                ldsm4(sKh + (jj * 16 + lr) * AT_SP + ks * 32 + lc * 16, t4);
                ldsm4(sKl + (jj * 16 + lr) * AT_SP + ks * 32 + lc * 16, u4);
                mma16816(s[2 * jj],     qh[ks], t4[0], t4[2]);
                mma16816(s[2 * jj],     qh[ks], u4[0], u4[2]);
                mma16816(s[2 * jj],     ql[ks], t4[0], t4[2]);
                mma16816(s[2 * jj + 1], qh[ks], t4[1], t4[3]);
                mma16816(s[2 * jj + 1], qh[ks], u4[1], u4[3]);
                mma16816(s[2 * jj + 1], ql[ks], t4[1], t4[3]);
            }
        }

        // --- scale + causal mask ---
        const bool diag = (kt * 64 + 63) > (qbase + w * 16);   // any col may exceed a row
#pragma unroll
        for (int j = 0; j < 8; j++)
#pragma unroll
            for (int e = 0; e < 4; e++) {
                float v = s[j][e] * 0.125f;
                if (diag) {
                    const int kvc = kt * 64 + j * 8 + tig * 2 + (e & 1);
                    const int qr  = qbase + w * 16 + g + ((e >> 1) << 3);
                    if (kvc > qr) v = -1e30f;
                }
                s[j][e] = v;
            }

        // --- online softmax ---
        float mx0 = -1e30f, mx1 = -1e30f;
#pragma unroll
        for (int j = 0; j < 8; j++) {
            mx0 = fmaxf(mx0, fmaxf(s[j][0], s[j][1]));
            mx1 = fmaxf(mx1, fmaxf(s[j][2], s[j][3]));
        }
        mx0 = fmaxf(mx0, __shfl_xor_sync(0xffffffffu, mx0, 1));
        mx0 = fmaxf(mx0, __shfl_xor_sync(0xffffffffu, mx0, 2));
        mx1 = fmaxf(mx1, __shfl_xor_sync(0xffffffffu, mx1, 1));
        mx1 = fmaxf(mx1, __shfl_xor_sync(0xffffffffu, mx1, 2));
        const float nm0 = fmaxf(m0r, mx0), nm1 = fmaxf(m1r, mx1);
        const float sc0 = __expf(m0r - nm0), sc1 = __expf(m1r - nm1);
        m0r = nm0; m1r = nm1;
        l0 *= sc0; l1 *= sc1;
#pragma unroll
        for (int j = 0; j < 8; j++) {
            o[j][0] *= sc0; o[j][1] *= sc0;
            o[j][2] *= sc1; o[j][3] *= sc1;
        }
#pragma unroll
        for (int j = 0; j < 8; j++) {
            s[j][0] = __expf(s[j][0] - nm0); s[j][1] = __expf(s[j][1] - nm0);
            s[j][2] = __expf(s[j][2] - nm1); s[j][3] = __expf(s[j][3] - nm1);
            l0 += s[j][0] + s[j][1];
            l1 += s[j][2] + s[j][3];
        }

        // --- O += (Ph+Pl)(Vh+Vl), 3 combos; V^T via ldmatrix.trans ---
#pragma unroll
        for (int ks = 0; ks < 4; ks++) {
            uint32_t pa[4], pl[4];
            {
                float r0, r1, r2, r3, r4, r5, r6, r7;
                bf16 b;
                b = __float2bfloat16(s[2 * ks][0]); r0 = s[2 * ks][0] - __bfloat162float(b);
                bf16 b1v = __float2bfloat16(s[2 * ks][1]); r1 = s[2 * ks][1] - __bfloat162float(b1v);
                pa[0] = ((uint32_t)__bfloat16_as_ushort(b1v) << 16) | __bfloat16_as_ushort(b);
                b = __float2bfloat16(s[2 * ks][2]); r2 = s[2 * ks][2] - __bfloat162float(b);
                b1v = __float2bfloat16(s[2 * ks][3]); r3 = s[2 * ks][3] - __bfloat162float(b1v);
                pa[1] = ((uint32_t)__bfloat16_as_ushort(b1v) << 16) | __bfloat16_as_ushort(b);
                b = __float2bfloat16(s[2 * ks + 1][0]); r4 = s[2 * ks + 1][0] - __bfloat162float(b);
                b1v = __float2bfloat16(s[2 * ks + 1][1]); r5 = s[2 * ks + 1][1] - __bfloat162float(b1v);
                pa[2] = ((uint32_t)__bfloat16_as_ushort(b1v) << 16) | __bfloat16_as_ushort(b);
                b = __float2bfloat16(s[2 * ks + 1][2]); r6 = s[2 * ks + 1][2] - __bfloat162float(b);
                b1v = __float2bfloat16(s[2 * ks + 1][3]); r7 = s[2 * ks + 1][3] - __bfloat162float(b1v);
                pa[3] = ((uint32_t)__bfloat16_as_ushort(b1v) << 16) | __bfloat16_as_ushort(b);
                pl[0] = pack_bf2(r0, r1); pl[1] = pack_bf2(r2, r3);
                pl[2] = pack_bf2(r4, r5); pl[3] = pack_bf2(r6, r7);
            }
#pragma unroll
            for (int jj = 0; jj < 4; jj++) {
                uint32_t t4[4], u4[4];
                ldsm4t(sVh + (ks * 16 + lr) * AT_SP + jj * 32 + lc * 16, t4);
                ldsm4t(sVl + (ks * 16 + lr) * AT_SP + jj * 32 + lc * 16, u4);
                mma16816(o[2 * jj],     pa, t4[0], t4[1]);
                mma16816(o[2 * jj],     pa, u4[0], u4[1]);
                mma16816(o[2 * jj],     pl, t4[0], t4[1]);
                mma16816(o[2 * jj + 1], pa, t4[2], t4[3]);
                mma16816(o[2 * jj + 1], pa, u4[2], u4[3]);
                mma16816(o[2 * jj + 1], pl, t4[2], t4[3]);
            }
        }
        __syncthreads();   // all warps done reading this stage before it is overwritten
    }

    // --- finalize ---
    l0 += __shfl_xor_sync(0xffffffffu, l0, 1);
    l0 += __shfl_xor_sync(0xffffffffu, l0, 2);
    l1 += __shfl_xor_sync(0xffffffffu, l1, 1);
    l1 += __shfl_xor_sync(0xffffffffu, l1, 2);
    const float i0 = 1.0f / l0, i1 = 1.0f / l1;

#pragma unroll
    for (int j = 0; j < 8; j++) {
        const int n = h * HD + j * 8 + tig * 2;
#pragma unroll
        for (int rr = 0; rr < 2; rr++) {
            const int mm = qbase + w * 16 + g + rr * 8;
            const float inv = rr ? i1 : i0;
            const float e = o[j][2 * rr] * inv;
            const float od = o[j][2 * rr + 1] * inv;
            bf16 he = __float2bfloat16(e), ho = __float2bfloat16(od);
            float le = e - __bfloat162float(he);
            float lo_ = od - __bfloat162float(ho);
            *(uint32_t*)(g_Ohi + (size_t)mm * D + n) =
                ((uint32_t)__bfloat16_as_ushort(ho) << 16) | __bfloat16_as_ushort(he);
            *(uint32_t*)(g_Olo + (size_t)mm * D + n) = pack_bf2(le, lo_);
        }
    }
}

// ---------------------------------------------------------------------------
extern "C" void kernel_launch(void* const* d_in, const int* in_sizes, int n_in,
                              void* d_out, int out_size) {
    (void)in_sizes; (void)n_in; (void)out_size;
    const float* x   = (const float*)d_in[0];
    const int*   pos = (const int*)  d_in[1];
    const float* Wq  = (const float*)d_in[2];
    const float* Wk  = (const float*)d_in[3];
    const float* Wv  = (const float*)d_in[4];
    const float* Wo  = (const float*)d_in[5];
    float* out = (float*)d_out;

    cudaFuncSetAttribute(mm_qkv_kernel, cudaFuncAttributeMaxDynamicSharedMemorySize, MM_SMEM);
    cudaFuncSetAttribute(mm_out_kernel, cudaFuncAttributeMaxDynamicSharedMemorySize, MM_SMEM);
    cudaFuncSetAttribute(attn_kernel, cudaFuncAttributeMaxDynamicSharedMemorySize, AT_SMEM);

    split_x_kernel<<<(S * D) / 256, 256>>>(x);
    split_w_kernel<<<dim3((D * D) / 256, 1, 4), 256>>>(Wq, Wk, Wv, Wo);
    rope_table_kernel<<<S, 32>>>(pos);

    mm_qkv_kernel<<<dim3(D / 128, S / 128, 3), 256, MM_SMEM>>>();
    attn_kernel<<<dim3(S / 128, H), 256, AT_SMEM>>>();
    mm_out_kernel<<<dim3(D / 128, S / 128, 1), 256, MM_SMEM>>>(out);
}

// round 6
// speedup vs baseline: 1.0887x; 1.0887x over previous
#include <cuda_runtime.h>
#include <cuda_bf16.h>
#include <cstdint>
#include <math.h>

#define S 4096
#define D 1024
#define H 16
#define HD 64
typedef __nv_bfloat16 bf16;

// ---------------- device scratch -------------------------------------------
__device__ bf16 g_Xhi[(size_t)S * D], g_Xlo[(size_t)S * D];
__device__ bf16 g_Whi[4 * (size_t)D * D], g_Wlo[4 * (size_t)D * D];
__device__ bf16 g_Qhi[(size_t)S * D], g_Qlo[(size_t)S * D];
__device__ bf16 g_Khi[(size_t)S * D], g_Klo[(size_t)S * D];
__device__ bf16 g_Vhi[(size_t)S * D], g_Vlo[(size_t)S * D];
__device__ bf16 g_Ohi[(size_t)S * D], g_Olo[(size_t)S * D];
__device__ float g_cos[S * 32], g_sin[S * 32];

// ---------------- helpers ---------------------------------------------------
__device__ __forceinline__ uint32_t smem_u32(const void* p) {
    uint32_t a;
    asm("{ .reg .u64 t; cvta.to.shared.u64 t, %1; cvt.u32.u64 %0, t; }"
        : "=r"(a) : "l"(p));
    return a;
}

__device__ __forceinline__ void cp16(uint32_t saddr, const void* g) {
    asm volatile("cp.async.cg.shared.global [%0], [%1], 16;" :: "r"(saddr), "l"(g));
}

__device__ __forceinline__ void ldsm4(uint32_t a, uint32_t r[4]) {
    asm volatile("ldmatrix.sync.aligned.m8n8.x4.shared.b16 {%0,%1,%2,%3}, [%4];"
                 : "=r"(r[0]), "=r"(r[1]), "=r"(r[2]), "=r"(r[3]) : "r"(a));
}

__device__ __forceinline__ void ldsm4t(uint32_t a, uint32_t r[4]) {
    asm volatile("ldmatrix.sync.aligned.m8n8.x4.trans.shared.b16 {%0,%1,%2,%3}, [%4];"
                 : "=r"(r[0]), "=r"(r[1]), "=r"(r[2]), "=r"(r[3]) : "r"(a));
}

__device__ __forceinline__ void mma16816(float c[4], const uint32_t a[4],
                                         uint32_t b0, uint32_t b1) {
    asm volatile(
        "mma.sync.aligned.m16n8k16.row.col.f32.bf16.bf16.f32 "
        "{%0,%1,%2,%3}, {%4,%5,%6,%7}, {%8,%9}, {%0,%1,%2,%3};"
        : "+f"(c[0]), "+f"(c[1]), "+f"(c[2]), "+f"(c[3])
        : "r"(a[0]), "r"(a[1]), "r"(a[2]), "r"(a[3]), "r"(b0), "r"(b1));
}

__device__ __forceinline__ uint32_t pack_bf2(float a, float b) {
    bf16 ha = __float2bfloat16(a), hb = __float2bfloat16(b);
    return ((uint32_t)__bfloat16_as_ushort(hb) << 16) | __bfloat16_as_ushort(ha);
}

// ---------------- split / rope-table kernels --------------------------------
__device__ __forceinline__ void split_one(const float* src, bf16* hi, bf16* lo, size_t i) {
    float x = src[i];
    bf16 h = __float2bfloat16(x);
    hi[i] = h;
    lo[i] = __float2bfloat16(x - __bfloat162float(h));
}

__global__ void split_x_kernel(const float* __restrict__ x) {
    size_t i = (size_t)blockIdx.x * 256 + threadIdx.x;
    split_one(x, g_Xhi, g_Xlo, i);
}

__global__ void split_w_kernel(const float* __restrict__ Wq, const float* __restrict__ Wk,
                               const float* __restrict__ Wv, const float* __restrict__ Wo) {
    int z = blockIdx.z;
    const float* W = (z == 0) ? Wq : (z == 1) ? Wk : (z == 2) ? Wv : Wo;
    size_t i = (size_t)blockIdx.x * 256 + threadIdx.x;
    split_one(W, g_Whi + (size_t)z * D * D, g_Wlo + (size_t)z * D * D, i);
}

__global__ void rope_table_kernel(const int* __restrict__ pos) {
    int m = blockIdx.x;
    int i = threadIdx.x;  // pair index 0..31
    double f = pow(10000.0, -(double)(2 * i) / 64.0);
    float ang = (float)pos[m] * (float)f;
    float sv, cv;
    sincosf(ang, &sv, &cv);
    g_cos[m * 32 + i] = cv;
    g_sin[m * 32 + i] = sv;
}

// ---------------- split-bf16 HMMA GEMM:  Y = A @ B^T -------------------------
// CTA 128x128, 4 warps (2x2), each warp 64x64 output. k-chunk 32, 2 stages.
#define MM_SP    80                 // padded row bytes (32 bf16 + 16B pad)
#define MM_MAT   (128 * MM_SP)      // 10240 B
#define MM_STAGE (4 * MM_MAT)       // Ah, Al, Bh, Bl
#define MM_SMEM  (2 * MM_STAGE)     // 81920 B

__device__ __forceinline__ void mm_load_stage(uint32_t sb, int st, int c,
                                              const bf16* A_h, const bf16* A_l,
                                              const bf16* B_h, const bf16* B_l) {
    const bf16* srcs[4] = {A_h, A_l, B_h, B_l};
    int t = threadIdx.x;
#pragma unroll
    for (int i = 0; i < 16; i++) {
        int cid = t + i * 128;                 // 0..2047
        int mi = cid >> 9;                     // matrix 0..3
        int r  = (cid >> 2) & 127;             // row 0..127
        int q  = cid & 3;                      // 16B chunk 0..3
        const bf16* g = srcs[mi] + (size_t)r * D + c * 32 + q * 8;
        cp16(sb + st * MM_STAGE + mi * MM_MAT + r * MM_SP + q * 16, g);
    }
}

__device__ __forceinline__ void mm_stage_compute(uint32_t so, int wm, int wn,
                                                 int lane, float acc[4][8][4]) {
    const int lr = lane & 15, lc = lane >> 4;
#pragma unroll
    for (int ks = 0; ks < 2; ks++) {
        uint32_t a4[4][4], bh[8][2], bl[8][2], t4[4];
#pragma unroll
        for (int i = 0; i < 4; i++)
            ldsm4(so + 0 * MM_MAT + (wm * 64 + i * 16 + lr) * MM_SP + ks * 32 + lc * 16, a4[i]);
#pragma unroll
        for (int jj = 0; jj < 4; jj++) {
            ldsm4(so + 2 * MM_MAT + (wn * 64 + jj * 16 + lr) * MM_SP + ks * 32 + lc * 16, t4);
            bh[2 * jj][0] = t4[0]; bh[2 * jj][1] = t4[2];
            bh[2 * jj + 1][0] = t4[1]; bh[2 * jj + 1][1] = t4[3];
            ldsm4(so + 3 * MM_MAT + (wn * 64 + jj * 16 + lr) * MM_SP + ks * 32 + lc * 16, t4);
            bl[2 * jj][0] = t4[0]; bl[2 * jj][1] = t4[2];
            bl[2 * jj + 1][0] = t4[1]; bl[2 * jj + 1][1] = t4[3];
        }
#pragma unroll
        for (int i = 0; i < 4; i++)
#pragma unroll
            for (int j = 0; j < 8; j++) {
                mma16816(acc[i][j], a4[i], bh[j][0], bh[j][1]);   // Ah*Bh
                mma16816(acc[i][j], a4[i], bl[j][0], bl[j][1]);   // Ah*Bl
            }
#pragma unroll
        for (int i = 0; i < 4; i++)
            ldsm4(so + 1 * MM_MAT + (wm * 64 + i * 16 + lr) * MM_SP + ks * 32 + lc * 16, a4[i]);
#pragma unroll
        for (int i = 0; i < 4; i++)
#pragma unroll
            for (int j = 0; j < 8; j++)
                mma16816(acc[i][j], a4[i], bh[j][0], bh[j][1]);   // Al*Bh
    }
}

// mode 0: rope + bf16 hi/lo out; mode 1: bf16 hi/lo out; mode 2: fp32 out.
__device__ void mm_body(const bf16* Ah, const bf16* Al, const bf16* Bh, const bf16* Bl,
                        int mode, float* outF, bf16* outH, bf16* outL) {
    extern __shared__ char smem[];
    uint32_t sb = smem_u32(smem);
    const int tid = threadIdx.x, lane = tid & 31, wid = tid >> 5;   // wid 0..3
    const int wm = wid >> 1, wn = wid & 1;
    const int m0 = blockIdx.y * 128, n0 = blockIdx.x * 128;

    const bf16* A_h = Ah + (size_t)m0 * D;
    const bf16* A_l = Al + (size_t)m0 * D;
    const bf16* B_h = Bh + (size_t)n0 * D;
    const bf16* B_l = Bl + (size_t)n0 * D;

    float acc[4][8][4];
#pragma unroll
    for (int i = 0; i < 4; i++)
#pragma unroll
        for (int j = 0; j < 8; j++)
#pragma unroll
            for (int e = 0; e < 4; e++) acc[i][j][e] = 0.0f;

    mm_load_stage(sb, 0, 0, A_h, A_l, B_h, B_l);
    asm volatile("cp.async.commit_group;" ::: "memory");

#pragma unroll 1
    for (int c = 0; c < 32; c++) {
        int st = c & 1;
        if (c + 1 < 32) {
            mm_load_stage(sb, st ^ 1, c + 1, A_h, A_l, B_h, B_l);
            asm volatile("cp.async.commit_group;" ::: "memory");
            asm volatile("cp.async.wait_group 1;" ::: "memory");
        } else {
            asm volatile("cp.async.wait_group 0;" ::: "memory");
        }
        __syncthreads();
        mm_stage_compute(sb + st * MM_STAGE, wm, wn, lane, acc);
        __syncthreads();
    }

    const int g = lane >> 2, tig = lane & 3;
#pragma unroll
    for (int i = 0; i < 4; i++)
#pragma unroll
        for (int j = 0; j < 8; j++) {
            const int m = m0 + wm * 64 + i * 16 + g;
            const int n = n0 + wn * 64 + j * 8 + tig * 2;
#pragma unroll
            for (int rr = 0; rr < 2; rr++) {
                const int mm = m + rr * 8;
                float e = acc[i][j][rr * 2], o = acc[i][j][rr * 2 + 1];
                if (mode == 0) {
                    const int pidx = (n & 63) >> 1;
                    const float cv = g_cos[mm * 32 + pidx];
                    const float sv = g_sin[mm * 32 + pidx];
                    const float e2 = e * cv - o * sv;
                    const float o2 = e * sv + o * cv;
                    e = e2; o = o2;
                }
                if (mode == 2) {
                    *(float2*)(outF + (size_t)mm * D + n) = make_float2(e, o);
                } else {
                    bf16 he = __float2bfloat16(e), ho = __float2bfloat16(o);
                    float le = e - __bfloat162float(he);
                    float lo_ = o - __bfloat162float(ho);
                    *(uint32_t*)(outH + (size_t)mm * D + n) =
                        ((uint32_t)__bfloat16_as_ushort(ho) << 16) | __bfloat16_as_ushort(he);
                    *(uint32_t*)(outL + (size_t)mm * D + n) = pack_bf2(le, lo_);
                }
            }
        }
}

__global__ __launch_bounds__(128, 2) void mm_qkv_kernel() {
    const int z = blockIdx.z;
    const bf16* Bh = g_Whi + (size_t)z * D * D;
    const bf16* Bl = g_Wlo + (size_t)z * D * D;
    bf16* oh = (z == 0) ? g_Qhi : (z == 1) ? g_Khi : g_Vhi;
    bf16* ol = (z == 0) ? g_Qlo : (z == 1) ? g_Klo : g_Vlo;
    mm_body(g_Xhi, g_Xlo, Bh, Bl, (z < 2) ? 0 : 1, (float*)0, oh, ol);
}

__global__ __launch_bounds__(128, 2) void mm_out_kernel(float* __restrict__ out) {
    mm_body(g_Ohi, g_Olo, g_Whi + 3ull * D * D, g_Wlo + 3ull * D * D, 2, out, (bf16*)0, (bf16*)0);
}

// ---------------- HMMA flash attention (R4 config) ---------------------------
// CTA = 64 q rows x 1 head, 4 warps (each m16). kv tiles of 64, single buffer.
#define AT_SP   144                 // padded row bytes (64 bf16 = 128B + 16B pad)
#define AT_MAT  (64 * AT_SP)        // 9216 B
#define AT_SMEM (6 * AT_MAT)        // Qh Ql Kh Kl Vh Vl = 55296 B

__device__ __forceinline__ void at_load64(uint32_t sdst, const bf16* g) {
    int t = threadIdx.x;
#pragma unroll
    for (int i = 0; i < 4; i++) {
        int cid = t + i * 128;         // 0..511
        int r = cid >> 3;              // row 0..63
        int q = cid & 7;               // 16B chunk 0..7 (128B per row)
        cp16(sdst + r * AT_SP + q * 16, g + (size_t)r * D + q * 8);
    }
}

__global__ __launch_bounds__(128) void attn_kernel() {
    extern __shared__ char smem[];
    uint32_t sb = smem_u32(smem);
    const int tid = threadIdx.x, lane = tid & 31, w = tid >> 5;
    const int qt = (int)gridDim.x - 1 - (int)blockIdx.x;   // heavy first
    const int h = blockIdx.y;
    const int qbase = qt * 64;
    const int lr = lane & 15, lc = lane >> 4;
    const int g = lane >> 2, tig = lane & 3;

    at_load64(sb + 0 * AT_MAT, g_Qhi + (size_t)qbase * D + h * HD);
    at_load64(sb + 1 * AT_MAT, g_Qlo + (size_t)qbase * D + h * HD);
    asm volatile("cp.async.commit_group;" ::: "memory");
    asm volatile("cp.async.wait_group 0;" ::: "memory");
    __syncthreads();

    uint32_t qh[4][4], ql[4][4];
#pragma unroll
    for (int ks = 0; ks < 4; ks++) {
        ldsm4(sb + 0 * AT_MAT + (w * 16 + lr) * AT_SP + ks * 32 + lc * 16, qh[ks]);
        ldsm4(sb + 1 * AT_MAT + (w * 16 + lr) * AT_SP + ks * 32 + lc * 16, ql[ks]);
    }

    float o[8][4];
#pragma unroll
    for (int j = 0; j < 8; j++)
#pragma unroll
        for (int e = 0; e < 4; e++) o[j][e] = 0.0f;
    float m0r = -1e30f, m1r = -1e30f, l0 = 0.0f, l1 = 0.0f;

#pragma unroll 1
    for (int kt = 0; kt <= qt; kt++) {
        const size_t koff = (size_t)(kt * 64) * D + h * HD;
        __syncthreads();   // all warps done reading smem from previous tile
        at_load64(sb + 2 * AT_MAT, g_Khi + koff);
        at_load64(sb + 3 * AT_MAT, g_Klo + koff);
        at_load64(sb + 4 * AT_MAT, g_Vhi + koff);
        at_load64(sb + 5 * AT_MAT, g_Vlo + koff);
        asm volatile("cp.async.commit_group;" ::: "memory");
        asm volatile("cp.async.wait_group 0;" ::: "memory");
        __syncthreads();

        float s[8][4];
#pragma unroll
        for (int j = 0; j < 8; j++)
#pragma unroll
            for (int e = 0; e < 4; e++) s[j][e] = 0.0f;

        // --- S = (Qh+Ql)(Kh+Kl)^T, 3 combos ---
#pragma unroll
        for (int ks = 0; ks < 4; ks++) {
#pragma unroll
            for (int jj = 0; jj < 4; jj++) {
                uint32_t t4[4], u4[4];
                ldsm4(sb + 2 * AT_MAT + (jj * 16 + lr) * AT_SP + ks * 32 + lc * 16, t4);
                ldsm4(sb + 3 * AT_MAT + (jj * 16 + lr) * AT_SP + ks * 32 + lc * 16, u4);
                mma16816(s[2 * jj],     qh[ks], t4[0], t4[2]);
                mma16816(s[2 * jj],     qh[ks], u4[0], u4[2]);
                mma16816(s[2 * jj],     ql[ks], t4[0], t4[2]);
                mma16816(s[2 * jj + 1], qh[ks], t4[1], t4[3]);
                mma16816(s[2 * jj + 1], qh[ks], u4[1], u4[3]);
                mma16816(s[2 * jj + 1], ql[ks], t4[1], t4[3]);
            }
        }

        // --- scale + causal mask (diag tile only) ---
        const bool diag = (kt == qt);
#pragma unroll
        for (int j = 0; j < 8; j++)
#pragma unroll
            for (int e = 0; e < 4; e++) {
                float v = s[j][e] * 0.125f;
                if (diag) {
                    const int kvc = kt * 64 + j * 8 + tig * 2 + (e & 1);
                    const int qr  = qbase + w * 16 + g + ((e >> 1) << 3);
                    if (kvc > qr) v = -1e30f;
                }
                s[j][e] = v;
            }

        // --- online softmax ---
        float mx0 = -1e30f, mx1 = -1e30f;
#pragma unroll
        for (int j = 0; j < 8; j++) {
            mx0 = fmaxf(mx0, fmaxf(s[j][0], s[j][1]));
            mx1 = fmaxf(mx1, fmaxf(s[j][2], s[j][3]));
        }
        mx0 = fmaxf(mx0, __shfl_xor_sync(0xffffffffu, mx0, 1));
        mx0 = fmaxf(mx0, __shfl_xor_sync(0xffffffffu, mx0, 2));
        mx1 = fmaxf(mx1, __shfl_xor_sync(0xffffffffu, mx1, 1));
        mx1 = fmaxf(mx1, __shfl_xor_sync(0xffffffffu, mx1, 2));
        const float nm0 = fmaxf(m0r, mx0), nm1 = fmaxf(m1r, mx1);
        const float sc0 = __expf(m0r - nm0), sc1 = __expf(m1r - nm1);
        m0r = nm0; m1r = nm1;
        l0 *= sc0; l1 *= sc1;
#pragma unroll
        for (int j = 0; j < 8; j++) {
            o[j][0] *= sc0; o[j][1] *= sc0;
            o[j][2] *= sc1; o[j][3] *= sc1;
        }
#pragma unroll
        for (int j = 0; j < 8; j++) {
            s[j][0] = __expf(s[j][0] - nm0); s[j][1] = __expf(s[j][1] - nm0);
            s[j][2] = __expf(s[j][2] - nm1); s[j][3] = __expf(s[j][3] - nm1);
            l0 += s[j][0] + s[j][1];
            l1 += s[j][2] + s[j][3];
        }

        // --- O += (Ph+Pl)(Vh+Vl), 3 combos; V^T via ldmatrix.trans ---
#pragma unroll
        for (int ks = 0; ks < 4; ks++) {
            uint32_t pa[4], pl[4];
            {
                float r0, r1, r2, r3, r4, r5, r6, r7;
                bf16 b;
                b = __float2bfloat16(s[2 * ks][0]); r0 = s[2 * ks][0] - __bfloat162float(b);
                bf16 b1v = __float2bfloat16(s[2 * ks][1]); r1 = s[2 * ks][1] - __bfloat162float(b1v);
                pa[0] = ((uint32_t)__bfloat16_as_ushort(b1v) << 16) | __bfloat16_as_ushort(b);
                b = __float2bfloat16(s[2 * ks][2]); r2 = s[2 * ks][2] - __bfloat162float(b);
                b1v = __float2bfloat16(s[2 * ks][3]); r3 = s[2 * ks][3] - __bfloat162float(b1v);
                pa[1] = ((uint32_t)__bfloat16_as_ushort(b1v) << 16) | __bfloat16_as_ushort(b);
                b = __float2bfloat16(s[2 * ks + 1][0]); r4 = s[2 * ks + 1][0] - __bfloat162float(b);
                b1v = __float2bfloat16(s[2 * ks + 1][1]); r5 = s[2 * ks + 1][1] - __bfloat162float(b1v);
                pa[2] = ((uint32_t)__bfloat16_as_ushort(b1v) << 16) | __bfloat16_as_ushort(b);
                b = __float2bfloat16(s[2 * ks + 1][2]); r6 = s[2 * ks + 1][2] - __bfloat162float(b);
                b1v = __float2bfloat16(s[2 * ks + 1][3]); r7 = s[2 * ks + 1][3] - __bfloat162float(b1v);
                pa[3] = ((uint32_t)__bfloat16_as_ushort(b1v) << 16) | __bfloat16_as_ushort(b);
                pl[0] = pack_bf2(r0, r1); pl[1] = pack_bf2(r2, r3);
                pl[2] = pack_bf2(r4, r5); pl[3] = pack_bf2(r6, r7);
            }
#pragma unroll
            for (int jj = 0; jj < 4; jj++) {
                uint32_t t4[4], u4[4];
                ldsm4t(sb + 4 * AT_MAT + (ks * 16 + lr) * AT_SP + jj * 32 + lc * 16, t4);
                ldsm4t(sb + 5 * AT_MAT + (ks * 16 + lr) * AT_SP + jj * 32 + lc * 16, u4);
                mma16816(o[2 * jj],     pa, t4[0], t4[1]);
                mma16816(o[2 * jj],     pa, u4[0], u4[1]);
                mma16816(o[2 * jj],     pl, t4[0], t4[1]);
                mma16816(o[2 * jj + 1], pa, t4[2], t4[3]);
                mma16816(o[2 * jj + 1], pa, u4[2], u4[3]);
                mma16816(o[2 * jj + 1], pl, t4[2], t4[3]);
            }
        }
    }

    // --- finalize ---
    l0 += __shfl_xor_sync(0xffffffffu, l0, 1);
    l0 += __shfl_xor_sync(0xffffffffu, l0, 2);
    l1 += __shfl_xor_sync(0xffffffffu, l1, 1);
    l1 += __shfl_xor_sync(0xffffffffu, l1, 2);
    const float i0 = 1.0f / l0, i1 = 1.0f / l1;

#pragma unroll
    for (int j = 0; j < 8; j++) {
        const int n = h * HD + j * 8 + tig * 2;
#pragma unroll
        for (int rr = 0; rr < 2; rr++) {
            const int mm = qbase + w * 16 + g + rr * 8;
            const float inv = rr ? i1 : i0;
            const float e = o[j][2 * rr] * inv;
            const float od = o[j][2 * rr + 1] * inv;
            bf16 he = __float2bfloat16(e), ho = __float2bfloat16(od);
            float le = e - __bfloat162float(he);
            float lo_ = od - __bfloat162float(ho);
            *(uint32_t*)(g_Ohi + (size_t)mm * D + n) =
                ((uint32_t)__bfloat16_as_ushort(ho) << 16) | __bfloat16_as_ushort(he);
            *(uint32_t*)(g_Olo + (size_t)mm * D + n) = pack_bf2(le, lo_);
        }
    }
}

// ---------------------------------------------------------------------------
extern "C" void kernel_launch(void* const* d_in, const int* in_sizes, int n_in,
                              void* d_out, int out_size) {
    (void)in_sizes; (void)n_in; (void)out_size;
    const float* x   = (const float*)d_in[0];
    const int*   pos = (const int*)  d_in[1];
    const float* Wq  = (const float*)d_in[2];
    const float* Wk  = (const float*)d_in[3];
    const float* Wv  = (const float*)d_in[4];
    const float* Wo  = (const float*)d_in[5];
    float* out = (float*)d_out;

    cudaFuncSetAttribute(mm_qkv_kernel, cudaFuncAttributeMaxDynamicSharedMemorySize, MM_SMEM);
    cudaFuncSetAttribute(mm_out_kernel, cudaFuncAttributeMaxDynamicSharedMemorySize, MM_SMEM);
    cudaFuncSetAttribute(attn_kernel, cudaFuncAttributeMaxDynamicSharedMemorySize, AT_SMEM);

    split_x_kernel<<<(S * D) / 256, 256>>>(x);
    split_w_kernel<<<dim3((D * D) / 256, 1, 4), 256>>>(Wq, Wk, Wv, Wo);
    rope_table_kernel<<<S, 32>>>(pos);

    mm_qkv_kernel<<<dim3(D / 128, S / 128, 3), 128, MM_SMEM>>>();
    attn_kernel<<<dim3(S / 64, H), 128, AT_SMEM>>>();
    mm_out_kernel<<<dim3(D / 128, S / 128, 1), 128, MM_SMEM>>>(out);
}